// round 9
// baseline (speedup 1.0000x reference)
#include <cuda_runtime.h>
#include <cuda_fp16.h>
#include <cstdint>

#define NROWS 8192
#define BHALF 4096
#define DIM   256
#define SS    72            // smem row stride (fp16): 64 data + 8 pad, conflict-free
#define STAGE (128 * SS)    // elems per array per pipeline stage (K=64 chunk)
#define NTILE 64
#define NBLK  2080          // upper-triangular 64x64 tile count
#define GRID  296           // persistent CTAs: all co-resident (<= 2/SM)
#define SMEM_BYTES (2 * 2 * STAGE * 2)   // 2 arrays x 2 stages x fp16 = 73728 B
#define ROWS_PER_CTA 28     // 296*28 >= 8192

// ---------------- scratch (device globals; no allocation) ----------------
__device__ __half g_Xh[NROWS * DIM];
__device__ float  g_sq[NROWS];
__device__ float  g_colpart[GRID * DIM];
__device__ float  g_c1;            // -g0 * log2(e)
__device__ double g_Wpart[GRID];
__device__ unsigned g_ctr1;        // prep barrier
__device__ unsigned g_flag;        // scalar ready
__device__ unsigned g_ctr3;        // completion ticket

// ---------------- asm helpers ----------------
__device__ __forceinline__ void mma16816(float* c, const uint32_t* a, const uint32_t* b) {
    asm volatile(
        "mma.sync.aligned.m16n8k16.row.col.f32.f16.f16.f32 "
        "{%0,%1,%2,%3},{%4,%5,%6,%7},{%8,%9},{%0,%1,%2,%3};"
        : "+f"(c[0]), "+f"(c[1]), "+f"(c[2]), "+f"(c[3])
        : "r"(a[0]), "r"(a[1]), "r"(a[2]), "r"(a[3]), "r"(b[0]), "r"(b[1]));
}

__device__ __forceinline__ void ldm_x4(uint32_t* r, uint32_t addr) {
    asm volatile("ldmatrix.sync.aligned.m8n8.x4.shared.b16 {%0,%1,%2,%3}, [%4];"
                 : "=r"(r[0]), "=r"(r[1]), "=r"(r[2]), "=r"(r[3]) : "r"(addr));
}

__device__ __forceinline__ void cpa16(uint32_t d, const void* s) {
    asm volatile("cp.async.cg.shared.global [%0], [%1], 16;" :: "r"(d), "l"(s));
}

__device__ __forceinline__ float kern_entry(float sq2, float g, float c1) {
    float d = fmaxf(fmaf(-2.f, g, sq2), 0.f);
    float p = d * c1;
    float e;
    asm("ex2.approx.f32 %0, %1;" : "=f"(e) : "f"(p));
    float e2 = e * e, e4 = e2 * e2, e8 = e4 * e4, e16 = e8 * e8;
    return ((e + e2) + (e4 + e8)) + e16;   // = 5 * averaged kernel value
}

// ---------------- single fused persistent kernel ----------------
__global__ __launch_bounds__(256, 2) void mmd_all(const float* __restrict__ s,
                                                  const float* __restrict__ t,
                                                  float* __restrict__ out) {
    extern __shared__ __half dsm[];
    __half* sA = dsm;                  // A fp16 (2 stages)
    __half* sB = dsm + 2 * STAGE;      // B fp16 (2 stages)
    __shared__ float sSqA[128], sSqB[128];
    __shared__ double swr[8];
    __shared__ double sh[256];
    __shared__ float s_c1;
    __shared__ int s_last;

    int tid = threadIdx.x, warp = tid >> 5, lane = tid & 31;
    int bx = blockIdx.x;

    // ================= Phase A: prep (fp16 image + row norms + column partials) ======
    {
        float colsum[8] = {0.f, 0.f, 0.f, 0.f, 0.f, 0.f, 0.f, 0.f};
        int base = bx * ROWS_PER_CTA;
#pragma unroll
        for (int i = warp; i < ROWS_PER_CTA; i += 8) {
            int row = base + i;
            if (row < NROWS) {
                const float* src = (row < BHALF) ? (s + (size_t)row * DIM)
                                                 : (t + (size_t)(row - BHALF) * DIM);
                float4 v0 = *(const float4*)(src + lane * 8);
                float4 v1 = *(const float4*)(src + lane * 8 + 4);
                float v[8] = {v0.x, v0.y, v0.z, v0.w, v1.x, v1.y, v1.z, v1.w};
                float sq = 0.f;
                unsigned hu[4];
#pragma unroll
                for (int j = 0; j < 4; j++) {
                    float a = v[2 * j], b = v[2 * j + 1];
                    sq = fmaf(a, a, sq);
                    sq = fmaf(b, b, sq);
                    colsum[2 * j]     += a;
                    colsum[2 * j + 1] += b;
                    hu[j] = (unsigned)__half_as_ushort(__float2half_rn(a)) |
                            ((unsigned)__half_as_ushort(__float2half_rn(b)) << 16);
                }
                *(uint4*)(g_Xh + (size_t)row * DIM + lane * 8) =
                    make_uint4(hu[0], hu[1], hu[2], hu[3]);
#pragma unroll
                for (int o = 16; o; o >>= 1) sq += __shfl_xor_sync(0xffffffffu, sq, o);
                if (lane == 0) g_sq[row] = sq;
            }
        }
        float* scol = (float*)dsm;     // reuse GEMM smem as [8][256] scratch
#pragma unroll
        for (int j = 0; j < 8; j++) scol[warp * 256 + lane * 8 + j] = colsum[j];
        __syncthreads();
        float a = 0.f;
#pragma unroll
        for (int w = 0; w < 8; w++) a += scol[w * 256 + tid];
        g_colpart[bx * DIM + tid] = a;
    }

    // ================= device-wide prep barrier (all CTAs resident) ==================
    __threadfence();
    __syncthreads();
    if (tid == 0) {
        atomicAdd(&g_ctr1, 1u);
        while (atomicAdd(&g_ctr1, 0u) < GRID) { }
    }
    __syncthreads();

    // ================= GEMM phase setup ==============================================
    int cnt   = (bx >= 1 && bx <= 8) ? 8 : 7;           // 2080 = 8*8 + 288*7
    int start = 7 * bx + min(max(bx - 1, 0), 8);

    int rem = start, bm = 0;
    while (rem >= NTILE - bm) { rem -= NTILE - bm; bm++; }
    int bn = bm + rem;
    int bmL = bm, bnL = bn;

    int wm = warp >> 1, wn = warp & 1;
    int lane4 = lane >> 2;
    int q2 = (lane & 3) * 2;
    int l8 = lane & 7;

    uint32_t uA = (uint32_t)__cvta_generic_to_shared(sA);
    uint32_t uB = (uint32_t)__cvta_generic_to_shared(sB);

    int aoff = (wm * 32 + ((lane >> 3) & 1) * 8 + l8) * SS + (lane >> 4) * 8;
    int boff = (wn * 64 + ((lane >> 4) & 1) * 8 + l8) * SS + ((lane >> 3) & 1) * 8;

    float acc[2][8][4];

#define LOAD_CHUNK(bmv, bnv, kc, st)                                           \
    {                                                                          \
        const __half* gA = g_Xh + (size_t)(bmv) * 128 * DIM;                   \
        const __half* gB = g_Xh + (size_t)(bnv) * 128 * DIM;                   \
        _Pragma("unroll")                                                      \
        for (int it = 0; it < 4; it++) {                                       \
            int idx = tid + it * 256;                                          \
            int row = idx >> 3, seg = idx & 7;                                 \
            size_t go = (size_t)row * DIM + (kc) * 64 + seg * 8;               \
            uint32_t so = (uint32_t)((st) * STAGE + row * SS + seg * 8) * 2;   \
            cpa16(uA + so, gA + go);                                           \
            cpa16(uB + so, gB + go);                                           \
        }                                                                      \
        asm volatile("cp.async.commit_group;" ::: "memory");                   \
    }

    int G = cnt * 4;
    LOAD_CHUNK(bmL, bnL, 0, 0);
    LOAD_CHUNK(bmL, bnL, 1, 1);

    // ======== CTA 0: bandwidth scalar, overlapped with everyone's pipeline ramp =====
    if (bx == 0) {
        double Sd = 0.0;
#pragma unroll 4
        for (int i = 0; i < 32; i++) Sd += (double)g_sq[tid + i * 256];
        double c = 0.0;
        for (int b = 0; b < GRID; b++) c += (double)g_colpart[b * DIM + tid];
        sh[tid] = 2.0 * (double)NROWS * Sd - 2.0 * c * c;
        __syncthreads();
        for (int o = 128; o; o >>= 1) {
            if (tid < o) sh[tid] += sh[tid + o];
            __syncthreads();
        }
        if (tid == 0) {
            double bw = ((double)NROWS * (double)NROWS - (double)NROWS) / sh[0];
            bw *= 0.25;  // / 2^(NUM_KERNELS//2)
            g_c1 = (float)(-bw * 1.4426950408889634);
            __threadfence();
            atomicExch(&g_flag, 1u);
        }
    }

    double accd = 0.0;
    bool need_c1 = true;

    // ================= persistent mainloop ==========================================
    for (int g = 0; g < G; g++) {
        int c = g & 3, st = g & 1;
        if (c == 0) {
            if (g > 0) { bn++; if (bn == NTILE) { bm++; bn = bm; } }
#pragma unroll
            for (int mf = 0; mf < 2; mf++)
#pragma unroll
                for (int nf = 0; nf < 8; nf++)
#pragma unroll
                    for (int k = 0; k < 4; k++) acc[mf][nf][k] = 0.f;
        }

        if (g + 1 < G) asm volatile("cp.async.wait_group 1;" ::: "memory");
        else           asm volatile("cp.async.wait_group 0;" ::: "memory");
        __syncthreads();

        uint32_t stB = (uint32_t)(st * STAGE) * 2;
#pragma unroll
        for (int ks = 0; ks < 4; ks++) {
            uint32_t kofs = stB + (uint32_t)(ks * 16) * 2;
            uint32_t ah[2][4], bh[4][4];
#pragma unroll
            for (int mf = 0; mf < 2; mf++)
                ldm_x4(ah[mf], uA + kofs + (uint32_t)((aoff + mf * 16 * SS) * 2));
#pragma unroll
            for (int p = 0; p < 4; p++)
                ldm_x4(bh[p], uB + kofs + (uint32_t)((boff + p * 16 * SS) * 2));
#pragma unroll
            for (int p = 0; p < 4; p++) {
#pragma unroll
                for (int mf = 0; mf < 2; mf++) mma16816(acc[mf][2 * p],     ah[mf], bh[p]);
#pragma unroll
                for (int mf = 0; mf < 2; mf++) mma16816(acc[mf][2 * p + 1], ah[mf], bh[p] + 2);
            }
        }
        __syncthreads();   // stage st free for reuse

        // issue loads for chunk g+2 (possibly next tile) BEFORE the epilogue
        if (g + 2 < G) {
            int c2 = (g + 2) & 3;
            if (c2 == 0) { bnL++; if (bnL == NTILE) { bmL++; bnL = bmL; } }
            LOAD_CHUNK(bmL, bnL, c2, (g + 2) & 1);
        }

        if (c == 3) {   // tile complete: fused RBF epilogue
            if (tid < 128) sSqA[tid] = g_sq[bm * 128 + tid];
            else           sSqB[tid - 128] = g_sq[bn * 128 + (tid - 128)];
            if (need_c1 && tid == 0) {
                while (atomicAdd(&g_flag, 0u) == 0u) { }
                __threadfence();
                s_c1 = g_c1;
            }
            __syncthreads();
            need_c1 = false;
            float c1 = s_c1;

            float wsum = 0.f;
            int r0 = wm * 32 + lane4;
#pragma unroll
            for (int mf = 0; mf < 2; mf++)
#pragma unroll
                for (int nf = 0; nf < 8; nf++) {
                    int rA = r0 + mf * 16;
                    int c0 = wn * 64 + nf * 8 + q2;
                    float s0 = sSqA[rA], s1 = sSqA[rA + 8];
                    float t0 = sSqB[c0], t1 = sSqB[c0 + 1];
                    wsum += kern_entry(s0 + t0, acc[mf][nf][0], c1);
                    wsum += kern_entry(s0 + t1, acc[mf][nf][1], c1);
                    wsum += kern_entry(s1 + t0, acc[mf][nf][2], c1);
                    wsum += kern_entry(s1 + t1, acc[mf][nf][3], c1);
                }

            double w = (double)wsum;
            if ((bm < 32) != (bn < 32)) w = -w;
            if (bm != bn) w *= 2.0;
            accd += w;
        }
    }

    // ================= per-CTA reduction + last-CTA final reduce =====================
#pragma unroll
    for (int o = 16; o; o >>= 1) accd += __shfl_down_sync(0xffffffffu, accd, o);
    if (lane == 0) swr[warp] = accd;
    __syncthreads();
    if (tid == 0) {
        double tot = 0.0;
#pragma unroll
        for (int i = 0; i < 8; i++) tot += swr[i];
        g_Wpart[bx] = tot;
        __threadfence();
        unsigned old = atomicAdd(&g_ctr3, 1u);
        s_last = (old == GRID - 1) ? 1 : 0;
    }
    __syncthreads();

    if (s_last) {
        __threadfence();
        double a = (tid < GRID) ? g_Wpart[tid] : 0.0;
        if (tid + 256 < GRID) a += g_Wpart[tid + 256];
        sh[tid] = a;
        __syncthreads();
        for (int o = 128; o; o >>= 1) {
            if (tid < o) sh[tid] += sh[tid + o];
            __syncthreads();
        }
        if (tid == 0) {
            out[0] = (float)(sh[0] / (5.0 * (double)BHALF * (double)BHALF));
            g_ctr1 = 0;        // reset for next graph replay (deterministic)
            g_flag = 0;
            g_ctr3 = 0;
        }
    }
}

// ---------------- launch ----------------
extern "C" void kernel_launch(void* const* d_in, const int* in_sizes, int n_in,
                              void* d_out, int out_size) {
    const float* s = (const float*)d_in[0];
    const float* t = (const float*)d_in[1];
    float* out = (float*)d_out;

    cudaFuncSetAttribute(mmd_all, cudaFuncAttributeMaxDynamicSharedMemorySize, SMEM_BYTES);
    mmd_all<<<GRID, 256, SMEM_BYTES>>>(s, t, out);
}